// round 13
// baseline (speedup 1.0000x reference)
#include <cuda_runtime.h>

#define KK 21
#define LDIM 256
#define CDIM 256
#define BDIM 4
#define EDGES 255
#define SLAB_P (EDGES*CDIM)          // 65280
#define SLAB_U (LDIM*CDIM)           // 65536
#define S_ELEMS (BDIM*KK*LDIM*CDIM)  // 5,505,024
#define P_ELEMS (BDIM*KK*KK*EDGES*CDIM) // 115,153,920

// Scratch (device globals: no allocation allowed)
__device__ float g_PhT[P_ELEMS];   // pairwise_h transposed: [B,K,K, w(255), h(256)]
__device__ float g_UhT[S_ELEMS];   // unary_h transposed:    [B,K, w, h]
__device__ float g_alpha[2][S_ELEMS];  // [dir][b,k,step,chain]  dir0=h, dir1=v
__device__ float g_beta[2][S_ELEMS];

__device__ __forceinline__ float ex2f(float x){ float y; asm("ex2.approx.f32 %0, %1;" : "=f"(y) : "f"(x)); return y; }
__device__ __forceinline__ float lg2f(float x){ float y; asm("lg2.approx.f32 %0, %1;" : "=f"(y) : "f"(x)); return y; }

__device__ __forceinline__ void cp16_pred(float* dst, const float* src, unsigned pred){
    unsigned su = (unsigned)__cvta_generic_to_shared(dst);
    asm volatile("{.reg .pred p; setp.ne.u32 p, %2, 0; @p cp.async.cg.shared.global [%0], [%1], 16;}"
                 :: "r"(su), "l"(src), "r"(pred));
}

// ---------------------------------------------------------------------------
// Chain scan worker. Block = 21 warps (state per warp) x 32 lanes (chains).
// Depth-3 cp.async smem pipeline for pairwise + unary; single barrier/step.
// ---------------------------------------------------------------------------
template<int BWD>
__device__ __forceinline__ void scan_dir(const float* __restrict__ P,
    const float* __restrict__ U, float* __restrict__ AB,
    int b, int c0, int wid, int lane, float sc, float gl,
    float* Pb, float* Ub, float* Sb)
{
    const long RS = BWD ? (long)SLAB_P : (long)KK * SLAB_P;   // row stride in floats
    const int rowsel = BWD ? wid * KK : wid;
    const float* gP = P + ((long)(b * KK * KK) + rowsel) * SLAB_P + c0;
    const float* gU = U + ((long)(b * KK) + wid) * SLAB_U + c0;
    int subrow = lane >> 3, chunk = lane & 7;

    auto issue = [&](int s, int buf) {
        int e  = BWD ? (254 - s) : s;        // edge index
        int up = BWD ? (254 - s) : (s + 1);  // unary position
        const float* srcRow = gP + (long)e * CDIM;
        const float* srcU   = gU + (long)up * CDIM;
        #pragma unroll
        for (int q = 0; q < 6; q++) {
            int row = q * 4 + subrow;
            cp16_pred(Pb + (((buf * 21 + wid) * 21 + row) * 32 + chunk * 4),
                      srcRow + (long)row * RS + chunk * 4,
                      (unsigned)(row < KK));
        }
        cp16_pred(Ub + ((buf * 21 + wid) * 32 + chunk * 4),
                  srcU + chunk * 4,
                  (unsigned)(subrow == 0));
        asm volatile("cp.async.commit_group;" ::: "memory");
    };

    issue(0, 0);
    issue(1, 1);

    // init state
    {
        int ipos = BWD ? (LDIM - 1) : 0;
        float u0 = gU[(long)ipos * CDIM + lane];
        Sb[wid * 32 + lane] = u0;                  // fwd: alpha0=u0 ; bwd: t=0+uL
        AB[((long)(b * KK) + wid) * SLAB_U + (long)ipos * CDIM + c0 + lane] = BWD ? 0.f : u0;
    }

    int sb = 0;
    long abbase = ((long)(b * KK) + wid) * SLAB_U + c0 + lane;
    for (int s = 0; s < 255; s++) {
        int cur = s % 3;
        asm volatile("cp.async.wait_group 1;" ::: "memory");
        __syncthreads();   // step-s tile visible; prev state visible; buf (s+2)%3 free
        int nxt = s + 2; if (nxt > 254) nxt = 254;   // dup issue keeps group count uniform
        issue(nxt, (s + 2) % 3);

        float pj[KK], st[KK];
        #pragma unroll
        for (int j = 0; j < KK; j++) pj[j] = Pb[((cur * 21 + wid) * 21 + j) * 32 + lane];
        #pragma unroll
        for (int j = 0; j < KK; j++) st[j] = Sb[(sb * 21 + j) * 32 + lane];
        float un = Ub[(cur * 21 + wid) * 32 + lane];

        float mx = st[0];
        #pragma unroll
        for (int j = 1; j < KK; j++) mx = fmaxf(mx, st[j]);
        float nm = -mx * sc;
        float e0 = 0.f, e1 = 0.f, e2 = 0.f;
        #pragma unroll
        for (int j = 0; j < KK; j++) {
            float t = ex2f(fmaf(pj[j], sc, fmaf(st[j], sc, nm)));
            if (j % 3 == 0) e0 += t; else if (j % 3 == 1) e1 += t; else e2 += t;
        }
        float lse = fmaf(gl, lg2f((e0 + e1) + e2), mx);   // g*logsumexp((st+p)/g)

        int ipos = BWD ? (254 - s) : (s + 1);
        float outv, newstate;
        if (!BWD) { outv = lse + un; newstate = outv; }     // alpha_i
        else      { outv = lse;      newstate = lse + un; } // beta_i ; t = beta+u
        AB[abbase + (long)ipos * CDIM] = outv;
        Sb[((sb ^ 1) * 21 + wid) * 32 + lane] = newstate;
        sb ^= 1;
    }
    asm volatile("cp.async.wait_group 0;" ::: "memory");
}

// ---------------------------------------------------------------------------
// K1: blocks 0..63 run the v-direction scans (no dependency on transpose);
//     blocks 64..147 cooperatively transpose pairwise_h and unary_h using
//     warp-private 32x32 smem tiles. Both phases are memory-bound and share
//     the chip's bandwidth concurrently.
// ---------------------------------------------------------------------------
__global__ __launch_bounds__(672, 1)
void k1_vscan_transpose(const float* __restrict__ pv, const float* __restrict__ uv,
                        const float* __restrict__ ph, const float* __restrict__ uh,
                        const float* __restrict__ gamma) {
    extern __shared__ float sm[];
    int bid = blockIdx.x;
    int wid  = threadIdx.x >> 5;
    int lane = threadIdx.x & 31;

    if (bid < 64) {
        float* Pb = sm;                        // [3][21][21][32]
        float* Ub = Pb + 3 * 21 * 21 * 32;     // [3][21][32]
        float* Sb = Ub + 3 * 21 * 32;          // [2][21][32]
        int bwd = bid >> 5;
        int grp = bid & 31;
        int b = grp >> 3;
        int c0 = (grp & 7) << 5;
        float g = fmaxf(gamma[0], 0.01f);
        float sc = (1.0f / g) * 1.4426950408889634f;
        float gl = g * 0.6931471805599453f;
        if (bwd) scan_dir<1>(pv, uv, g_beta[1],  b, c0, wid, lane, sc, gl, Pb, Ub, Sb);
        else     scan_dir<0>(pv, uv, g_alpha[1], b, c0, wid, lane, sc, gl, Pb, Ub, Sb);
    } else {
        // warp-private tiled transpose
        float* Tw = sm + wid * (32 * 33);
        const int NW = 84 * 21;                 // total transpose warps
        int gw = (bid - 64) * 21 + wid;
        const int TP = 1764 * 64;               // ph tiles: (B*K*K) slabs x 64 tiles
        const int TU = 84 * 64;                 // uh tiles: (B*K) slabs x 64 tiles
        for (int t = gw; t < TP + TU; t += NW) {
            const float* ip; float* op; int cols;
            int slab, tt;
            if (t < TP) { slab = t >> 6; tt = t & 63; cols = 255;
                          ip = ph + (long)slab * (256 * 255);
                          op = g_PhT + (long)slab * (255 * 256); }
            else        { int t2 = t - TP; slab = t2 >> 6; tt = t2 & 63; cols = 256;
                          ip = uh + (long)slab * 65536;
                          op = g_UhT + (long)slab * 65536; }
            int r0 = (tt >> 3) << 5, c0 = (tt & 7) << 5;
            int cc = c0 + lane;
            bool cok = cc < cols;
            #pragma unroll 8
            for (int r = 0; r < 32; r++)
                Tw[r * 33 + lane] = cok ? __ldcs(&ip[(long)(r0 + r) * cols + cc]) : 0.f;
            __syncwarp();
            #pragma unroll 8
            for (int r2 = 0; r2 < 32; r2++) {
                int c = c0 + r2;
                if (c < cols) __stcs(&op[(long)c * 256 + r0 + lane], Tw[lane * 33 + r2]);
            }
            __syncwarp();
        }
    }
}

// ---------------------------------------------------------------------------
// K2: blocks 0..63 run the h-direction scans (consume g_PhT/g_UhT);
//     blocks 64..147 compute the v-marginal mv -> out+3S (consumes K1's
//     alpha[1]/beta[1]), filling the bandwidth the 64 scan blocks leave idle.
// ---------------------------------------------------------------------------
__global__ __launch_bounds__(672, 1)
void k2_hscan_margv(const float* __restrict__ gamma, float* __restrict__ out) {
    extern __shared__ float sm[];
    int bid = blockIdx.x;
    int wid  = threadIdx.x >> 5;
    int lane = threadIdx.x & 31;
    float g = fmaxf(gamma[0], 0.01f);
    float sc = (1.0f / g) * 1.4426950408889634f;

    if (bid < 64) {
        float* Pb = sm;
        float* Ub = Pb + 3 * 21 * 21 * 32;
        float* Sb = Ub + 3 * 21 * 32;
        int bwd = bid >> 5;
        int grp = bid & 31;
        int b = grp >> 3;
        int c0 = (grp & 7) << 5;
        float gl = g * 0.6931471805599453f;
        if (bwd) scan_dir<1>(g_PhT, g_UhT, g_beta[0],  b, c0, wid, lane, sc, gl, Pb, Ub, Sb);
        else     scan_dir<0>(g_PhT, g_UhT, g_alpha[0], b, c0, wid, lane, sc, gl, Pb, Ub, Sb);
    } else {
        // mv marginal, striped over 84 blocks x 672 threads
        float* mv_out = out + 3 * (size_t)S_ELEMS;
        const float* A = g_alpha[1];
        const float* Bt = g_beta[1];
        int stride = 84 * 672;
        for (int idx = (bid - 64) * 672 + threadIdx.x; idx < BDIM * SLAB_U; idx += stride) {
            int b = idx >> 16;
            int r = idx & 65535;
            int base = b * KK * SLAB_U + r;
            float s[KK];
            float m = -3.0e38f;
            #pragma unroll
            for (int k = 0; k < KK; k++) {
                s[k] = __ldcs(&A[base + k * SLAB_U]) + __ldcs(&Bt[base + k * SLAB_U]);
                m = fmaxf(m, s[k]);
            }
            float nm = -m * sc;
            float sum = 0.f;
            #pragma unroll
            for (int k = 0; k < KK; k++) {
                s[k] = ex2f(fmaf(s[k], sc, nm));
                sum += s[k];
            }
            float inv = __fdividef(1.0f, sum);
            #pragma unroll
            for (int k = 0; k < KK; k++) mv_out[base + k * SLAB_U] = s[k] * inv;
        }
    }
}

// ---------------------------------------------------------------------------
// K3: h-marginal (storage [b,k,w,h] -> output [b,k,h,w] via 32x32 smem tile)
//     fused with the combine step: reads mv/uh/uv, writes mh, new_uh, new_uv.
// ---------------------------------------------------------------------------
__global__ __launch_bounds__(1024)
void k3_margh_combine(const float* __restrict__ uh, const float* __restrict__ uv,
                      float* __restrict__ out, const float* __restrict__ gamma) {
    __shared__ float tile[32][33];
    int b = blockIdx.z;
    int w0 = blockIdx.y * 32, h0 = blockIdx.x * 32;
    int tx = threadIdx.x, ty = threadIdx.y;
    const float* A = g_alpha[0];
    const float* Bt = g_beta[0];
    float g = fmaxf(gamma[0], 0.01f);
    float sc = (1.0f / g) * 1.4426950408889634f;

    int base = b * KK * SLAB_U + (w0 + ty) * 256 + (h0 + tx);
    float s[KK];
    float m = -3.0e38f;
    #pragma unroll
    for (int k = 0; k < KK; k++) {
        s[k] = __ldcs(&A[base + k * SLAB_U]) + __ldcs(&Bt[base + k * SLAB_U]);
        m = fmaxf(m, s[k]);
    }
    float nm = -m * sc;
    float sum = 0.f;
    #pragma unroll
    for (int k = 0; k < KK; k++) {
        s[k] = ex2f(fmaf(s[k], sc, nm));
        sum += s[k];
    }
    float inv = __fdividef(1.0f, sum);

    float* mh_out = out + 2 * (size_t)S_ELEMS;
    const float* mv = out + 3 * (size_t)S_ELEMS;
    const float cc = 1.0f / 512.0f;
    int wbase = b * KK * SLAB_U + (h0 + ty) * 256 + (w0 + tx);
    #pragma unroll
    for (int k = 0; k < KK; k++) {
        __syncthreads();
        tile[ty][tx] = s[k] * inv;
        __syncthreads();
        int o = wbase + k * SLAB_U;
        float mhv = tile[tx][ty];
        mh_out[o] = mhv;
        float d = (mhv - mv[o]) * cc;
        out[o] = uh[o] - d;                          // new_uh
        out[o + (size_t)S_ELEMS] = uv[o] + d;        // new_uv
    }
}

extern "C" void kernel_launch(void* const* d_in, const int* in_sizes, int n_in,
                              void* d_out, int out_size) {
    const float* uh    = (const float*)d_in[0];
    const float* uv    = (const float*)d_in[1];
    const float* ph    = (const float*)d_in[2];
    const float* pv    = (const float*)d_in[3];
    const float* gamma = (const float*)d_in[4];
    float* out = (float*)d_out;

    const int smem_bytes = (3*21*21*32 + 3*21*32 + 2*21*32) * 4;  // 182,784
    cudaFuncSetAttribute(k1_vscan_transpose, cudaFuncAttributeMaxDynamicSharedMemorySize, smem_bytes);
    cudaFuncSetAttribute(k2_hscan_margv,     cudaFuncAttributeMaxDynamicSharedMemorySize, smem_bytes);

    // K1: v-scans (64 blocks) + ph/uh transpose (84 blocks), fully concurrent
    k1_vscan_transpose<<<148, 672, smem_bytes>>>(pv, uv, ph, uh, gamma);

    // K2: h-scans (64 blocks) + mv marginal (84 blocks)
    k2_hscan_margv<<<148, 672, smem_bytes>>>(gamma, out);

    // K3: mh marginal + combine (fused)
    {
        dim3 grid(8, 8, BDIM);
        dim3 blk(32, 32);
        k3_margh_combine<<<grid, blk>>>(uh, uv, out, gamma);
    }
    (void)in_sizes; (void)n_in; (void)out_size;
}

// round 14
// speedup vs baseline: 1.0320x; 1.0320x over previous
#include <cuda_runtime.h>

#define KK 21
#define LDIM 256
#define CDIM 256
#define BDIM 4
#define EDGES 255
#define SLAB_P (EDGES*CDIM)          // 65280
#define SLAB_U (LDIM*CDIM)           // 65536
#define S_ELEMS (BDIM*KK*LDIM*CDIM)  // 5,505,024
#define P_ELEMS (BDIM*KK*KK*EDGES*CDIM) // 115,153,920

// Scratch (device globals: no allocation allowed)
__device__ float g_PhT[P_ELEMS];   // pairwise_h transposed: [B,K,K, w(255), h(256)]
__device__ float g_UhT[S_ELEMS];   // unary_h transposed:    [B,K, w, h]
__device__ float g_alpha[2][S_ELEMS];  // [dir][b,k,step,chain]  dir0=h, dir1=v
__device__ float g_beta[2][S_ELEMS];

__device__ __forceinline__ float ex2f(float x){ float y; asm("ex2.approx.f32 %0, %1;" : "=f"(y) : "f"(x)); return y; }
__device__ __forceinline__ float lg2f(float x){ float y; asm("lg2.approx.f32 %0, %1;" : "=f"(y) : "f"(x)); return y; }

__device__ __forceinline__ void cp16_pred(float* dst, const float* src, unsigned pred){
    unsigned su = (unsigned)__cvta_generic_to_shared(dst);
    asm volatile("{.reg .pred p; setp.ne.u32 p, %2, 0; @p cp.async.cg.shared.global [%0], [%1], 16;}"
                 :: "r"(su), "l"(src), "r"(pred));
}

// ---------------------------------------------------------------------------
// Chain scan worker. Block = 21 warps (state per warp) x 32 lanes (chains).
// Depth-3 cp.async smem pipeline for pairwise + unary; single barrier/step.
// ---------------------------------------------------------------------------
template<int BWD>
__device__ __forceinline__ void scan_dir(const float* __restrict__ P,
    const float* __restrict__ U, float* __restrict__ AB,
    int b, int c0, int wid, int lane, float sc, float gl,
    float* Pb, float* Ub, float* Sb)
{
    const long RS = BWD ? (long)SLAB_P : (long)KK * SLAB_P;   // row stride in floats
    const int rowsel = BWD ? wid * KK : wid;
    const float* gP = P + ((long)(b * KK * KK) + rowsel) * SLAB_P + c0;
    const float* gU = U + ((long)(b * KK) + wid) * SLAB_U + c0;
    int subrow = lane >> 3, chunk = lane & 7;

    auto issue = [&](int s, int buf) {
        int e  = BWD ? (254 - s) : s;        // edge index
        int up = BWD ? (254 - s) : (s + 1);  // unary position
        const float* srcRow = gP + (long)e * CDIM;
        const float* srcU   = gU + (long)up * CDIM;
        #pragma unroll
        for (int q = 0; q < 6; q++) {
            int row = q * 4 + subrow;
            cp16_pred(Pb + (((buf * 21 + wid) * 21 + row) * 32 + chunk * 4),
                      srcRow + (long)row * RS + chunk * 4,
                      (unsigned)(row < KK));
        }
        cp16_pred(Ub + ((buf * 21 + wid) * 32 + chunk * 4),
                  srcU + chunk * 4,
                  (unsigned)(subrow == 0));
        asm volatile("cp.async.commit_group;" ::: "memory");
    };

    issue(0, 0);
    issue(1, 1);

    // init state
    {
        int ipos = BWD ? (LDIM - 1) : 0;
        float u0 = gU[(long)ipos * CDIM + lane];
        Sb[wid * 32 + lane] = u0;                  // fwd: alpha0=u0 ; bwd: t=0+uL
        AB[((long)(b * KK) + wid) * SLAB_U + (long)ipos * CDIM + c0 + lane] = BWD ? 0.f : u0;
    }

    int sb = 0;
    long abbase = ((long)(b * KK) + wid) * SLAB_U + c0 + lane;
    for (int s = 0; s < 255; s++) {
        int cur = s % 3;
        asm volatile("cp.async.wait_group 1;" ::: "memory");
        __syncthreads();   // step-s tile visible; prev state visible; buf (s+2)%3 free
        int nxt = s + 2; if (nxt > 254) nxt = 254;   // dup issue keeps group count uniform
        issue(nxt, (s + 2) % 3);

        float pj[KK], st[KK];
        #pragma unroll
        for (int j = 0; j < KK; j++) pj[j] = Pb[((cur * 21 + wid) * 21 + j) * 32 + lane];
        #pragma unroll
        for (int j = 0; j < KK; j++) st[j] = Sb[(sb * 21 + j) * 32 + lane];
        float un = Ub[(cur * 21 + wid) * 32 + lane];

        float mx = st[0];
        #pragma unroll
        for (int j = 1; j < KK; j++) mx = fmaxf(mx, st[j]);
        float nm = -mx * sc;
        float e0 = 0.f, e1 = 0.f, e2 = 0.f;
        #pragma unroll
        for (int j = 0; j < KK; j++) {
            float t = ex2f(fmaf(pj[j], sc, fmaf(st[j], sc, nm)));
            if (j % 3 == 0) e0 += t; else if (j % 3 == 1) e1 += t; else e2 += t;
        }
        float lse = fmaf(gl, lg2f((e0 + e1) + e2), mx);   // g*logsumexp((st+p)/g)

        int ipos = BWD ? (254 - s) : (s + 1);
        float outv, newstate;
        if (!BWD) { outv = lse + un; newstate = outv; }     // alpha_i
        else      { outv = lse;      newstate = lse + un; } // beta_i ; t = beta+u
        AB[abbase + (long)ipos * CDIM] = outv;
        Sb[((sb ^ 1) * 21 + wid) * 32 + lane] = newstate;
        sb ^= 1;
    }
    asm volatile("cp.async.wait_group 0;" ::: "memory");
}

// ---------------------------------------------------------------------------
// K1: blocks 0..63 run the v-direction scans (no dependency on transpose);
//     blocks 64..147 cooperatively transpose pairwise_h and unary_h using
//     warp-private 32x32 smem tiles. Both phases are memory-bound and share
//     the chip's bandwidth concurrently.
// ---------------------------------------------------------------------------
__global__ __launch_bounds__(672, 1)
void k1_vscan_transpose(const float* __restrict__ pv, const float* __restrict__ uv,
                        const float* __restrict__ ph, const float* __restrict__ uh,
                        const float* __restrict__ gamma) {
    extern __shared__ float sm[];
    int bid = blockIdx.x;
    int wid  = threadIdx.x >> 5;
    int lane = threadIdx.x & 31;

    if (bid < 64) {
        float* Pb = sm;                        // [3][21][21][32]
        float* Ub = Pb + 3 * 21 * 21 * 32;     // [3][21][32]
        float* Sb = Ub + 3 * 21 * 32;          // [2][21][32]
        int bwd = bid >> 5;
        int grp = bid & 31;
        int b = grp >> 3;
        int c0 = (grp & 7) << 5;
        float g = fmaxf(gamma[0], 0.01f);
        float sc = (1.0f / g) * 1.4426950408889634f;
        float gl = g * 0.6931471805599453f;
        if (bwd) scan_dir<1>(pv, uv, g_beta[1],  b, c0, wid, lane, sc, gl, Pb, Ub, Sb);
        else     scan_dir<0>(pv, uv, g_alpha[1], b, c0, wid, lane, sc, gl, Pb, Ub, Sb);
    } else {
        // warp-private tiled transpose
        float* Tw = sm + wid * (32 * 33);
        const int NW = 84 * 21;                 // total transpose warps
        int gw = (bid - 64) * 21 + wid;
        const int TP = 1764 * 64;               // ph tiles: (B*K*K) slabs x 64 tiles
        const int TU = 84 * 64;                 // uh tiles: (B*K) slabs x 64 tiles
        for (int t = gw; t < TP + TU; t += NW) {
            const float* ip; float* op; int cols;
            int slab, tt;
            if (t < TP) { slab = t >> 6; tt = t & 63; cols = 255;
                          ip = ph + (long)slab * (256 * 255);
                          op = g_PhT + (long)slab * (255 * 256); }
            else        { int t2 = t - TP; slab = t2 >> 6; tt = t2 & 63; cols = 256;
                          ip = uh + (long)slab * 65536;
                          op = g_UhT + (long)slab * 65536; }
            int r0 = (tt >> 3) << 5, c0 = (tt & 7) << 5;
            int cc = c0 + lane;
            bool cok = cc < cols;
            #pragma unroll 8
            for (int r = 0; r < 32; r++)
                Tw[r * 33 + lane] = cok ? __ldcs(&ip[(long)(r0 + r) * cols + cc]) : 0.f;
            __syncwarp();
            #pragma unroll 8
            for (int r2 = 0; r2 < 32; r2++) {
                int c = c0 + r2;
                if (c < cols) __stcs(&op[(long)c * 256 + r0 + lane], Tw[lane * 33 + r2]);
            }
            __syncwarp();
        }
    }
}

// ---------------------------------------------------------------------------
// K2: blocks 0..63 run the h-direction scans (consume g_PhT/g_UhT);
//     blocks 64..147 compute the v-marginal mv -> out+3S (consumes K1's
//     alpha[1]/beta[1]), filling the bandwidth the 64 scan blocks leave idle.
// ---------------------------------------------------------------------------
__global__ __launch_bounds__(672, 1)
void k2_hscan_margv(const float* __restrict__ gamma, float* __restrict__ out) {
    extern __shared__ float sm[];
    int bid = blockIdx.x;
    int wid  = threadIdx.x >> 5;
    int lane = threadIdx.x & 31;
    float g = fmaxf(gamma[0], 0.01f);
    float sc = (1.0f / g) * 1.4426950408889634f;

    if (bid < 64) {
        float* Pb = sm;
        float* Ub = Pb + 3 * 21 * 21 * 32;
        float* Sb = Ub + 3 * 21 * 32;
        int bwd = bid >> 5;
        int grp = bid & 31;
        int b = grp >> 3;
        int c0 = (grp & 7) << 5;
        float gl = g * 0.6931471805599453f;
        if (bwd) scan_dir<1>(g_PhT, g_UhT, g_beta[0],  b, c0, wid, lane, sc, gl, Pb, Ub, Sb);
        else     scan_dir<0>(g_PhT, g_UhT, g_alpha[0], b, c0, wid, lane, sc, gl, Pb, Ub, Sb);
    } else {
        // mv marginal, striped over 84 blocks x 672 threads
        float* mv_out = out + 3 * (size_t)S_ELEMS;
        const float* A = g_alpha[1];
        const float* Bt = g_beta[1];
        int stride = 84 * 672;
        for (int idx = (bid - 64) * 672 + threadIdx.x; idx < BDIM * SLAB_U; idx += stride) {
            int b = idx >> 16;
            int r = idx & 65535;
            int base = b * KK * SLAB_U + r;
            float s[KK];
            float m = -3.0e38f;
            #pragma unroll
            for (int k = 0; k < KK; k++) {
                s[k] = __ldcs(&A[base + k * SLAB_U]) + __ldcs(&Bt[base + k * SLAB_U]);
                m = fmaxf(m, s[k]);
            }
            float nm = -m * sc;
            float sum = 0.f;
            #pragma unroll
            for (int k = 0; k < KK; k++) {
                s[k] = ex2f(fmaf(s[k], sc, nm));
                sum += s[k];
            }
            float inv = __fdividef(1.0f, sum);
            #pragma unroll
            for (int k = 0; k < KK; k++) mv_out[base + k * SLAB_U] = s[k] * inv;
        }
    }
}

// ---------------------------------------------------------------------------
// K3: h-marginal (storage [b,k,w,h] -> output [b,k,h,w] via 32x32 smem tile)
//     fused with the combine step: reads mv/uh/uv, writes mh, new_uh, new_uv.
// ---------------------------------------------------------------------------
__global__ __launch_bounds__(1024)
void k3_margh_combine(const float* __restrict__ uh, const float* __restrict__ uv,
                      float* __restrict__ out, const float* __restrict__ gamma) {
    __shared__ float tile[32][33];
    int b = blockIdx.z;
    int w0 = blockIdx.y * 32, h0 = blockIdx.x * 32;
    int tx = threadIdx.x, ty = threadIdx.y;
    const float* A = g_alpha[0];
    const float* Bt = g_beta[0];
    float g = fmaxf(gamma[0], 0.01f);
    float sc = (1.0f / g) * 1.4426950408889634f;

    int base = b * KK * SLAB_U + (w0 + ty) * 256 + (h0 + tx);
    float s[KK];
    float m = -3.0e38f;
    #pragma unroll
    for (int k = 0; k < KK; k++) {
        s[k] = __ldcs(&A[base + k * SLAB_U]) + __ldcs(&Bt[base + k * SLAB_U]);
        m = fmaxf(m, s[k]);
    }
    float nm = -m * sc;
    float sum = 0.f;
    #pragma unroll
    for (int k = 0; k < KK; k++) {
        s[k] = ex2f(fmaf(s[k], sc, nm));
        sum += s[k];
    }
    float inv = __fdividef(1.0f, sum);

    float* mh_out = out + 2 * (size_t)S_ELEMS;
    const float* mv = out + 3 * (size_t)S_ELEMS;
    const float cc = 1.0f / 512.0f;
    int wbase = b * KK * SLAB_U + (h0 + ty) * 256 + (w0 + tx);
    #pragma unroll
    for (int k = 0; k < KK; k++) {
        __syncthreads();
        tile[ty][tx] = s[k] * inv;
        __syncthreads();
        int o = wbase + k * SLAB_U;
        float mhv = tile[tx][ty];
        mh_out[o] = mhv;
        float d = (mhv - mv[o]) * cc;
        out[o] = uh[o] - d;                          // new_uh
        out[o + (size_t)S_ELEMS] = uv[o] + d;        // new_uv
    }
}

extern "C" void kernel_launch(void* const* d_in, const int* in_sizes, int n_in,
                              void* d_out, int out_size) {
    const float* uh    = (const float*)d_in[0];
    const float* uv    = (const float*)d_in[1];
    const float* ph    = (const float*)d_in[2];
    const float* pv    = (const float*)d_in[3];
    const float* gamma = (const float*)d_in[4];
    float* out = (float*)d_out;

    const int smem_bytes = (3*21*21*32 + 3*21*32 + 2*21*32) * 4;  // 182,784
    cudaFuncSetAttribute(k1_vscan_transpose, cudaFuncAttributeMaxDynamicSharedMemorySize, smem_bytes);
    cudaFuncSetAttribute(k2_hscan_margv,     cudaFuncAttributeMaxDynamicSharedMemorySize, smem_bytes);

    // K1: v-scans (64 blocks) + ph/uh transpose (84 blocks), fully concurrent
    k1_vscan_transpose<<<148, 672, smem_bytes>>>(pv, uv, ph, uh, gamma);

    // K2: h-scans (64 blocks) + mv marginal (84 blocks)
    k2_hscan_margv<<<148, 672, smem_bytes>>>(gamma, out);

    // K3: mh marginal + combine (fused)
    {
        dim3 grid(8, 8, BDIM);
        dim3 blk(32, 32);
        k3_margh_combine<<<grid, blk>>>(uh, uv, out, gamma);
    }
    (void)in_sizes; (void)n_in; (void)out_size;
}

// round 15
// speedup vs baseline: 1.2540x; 1.2151x over previous
#include <cuda_runtime.h>

#define KK 21
#define LDIM 256
#define CDIM 256
#define BDIM 4
#define EDGES 255
#define SLAB_P (EDGES*CDIM)          // 65280
#define SLAB_U (LDIM*CDIM)           // 65536
#define S_ELEMS (BDIM*KK*LDIM*CDIM)  // 5,505,024
#define P_ELEMS (BDIM*KK*KK*EDGES*CDIM) // 115,153,920

// Scratch (device globals: no allocation allowed)
__device__ short g_PhT16[P_ELEMS];     // pairwise_h transposed+quantized: [B,K,K,w,h], value*4096
__device__ float g_UhT[S_ELEMS];       // unary_h transposed: [B,K,w,h]
__device__ float g_alpha[2][S_ELEMS];  // [dir][b,k,step,chain]  dir0=h, dir1=v
__device__ float g_beta[2][S_ELEMS];

__device__ __forceinline__ float ex2f(float x){ float y; asm("ex2.approx.f32 %0, %1;" : "=f"(y) : "f"(x)); return y; }
__device__ __forceinline__ float lg2f(float x){ float y; asm("lg2.approx.f32 %0, %1;" : "=f"(y) : "f"(x)); return y; }

__device__ __forceinline__ void cp16_pred(void* dst, const void* src, unsigned pred){
    unsigned su = (unsigned)__cvta_generic_to_shared(dst);
    asm volatile("{.reg .pred p; setp.ne.u32 p, %2, 0; @p cp.async.cg.shared.global [%0], [%1], 16;}"
                 :: "r"(su), "l"(src), "r"(pred));
}

// ---------------------------------------------------------------------------
// K0a: transpose + quantize pairwise_h [B,K,K,H,255] -> s16 [B,K,K,255,H]
// ---------------------------------------------------------------------------
__global__ void k0_ph(const float* __restrict__ ph) {
    __shared__ float tile[32][33];
    int slab = blockIdx.z;
    int c0 = blockIdx.x * 32, r0 = blockIdx.y * 32;
    int tx = threadIdx.x, ty = threadIdx.y;
    const float* ip = ph + (long)slab * (256 * 255);
    short* op = g_PhT16 + (long)slab * (255 * 256);

    #pragma unroll
    for (int m = 0; m < 4; m++) {
        int r = r0 + ty + 8*m, c = c0 + tx;
        if (c < 255) tile[ty + 8*m][tx] = __ldcs(&ip[r * 255 + c]);
    }
    __syncthreads();
    #pragma unroll
    for (int m = 0; m < 4; m++) {
        int c = c0 + ty + 8*m, r = r0 + tx;
        if (c < 255) {
            float v = tile[tx][ty + 8*m];
            int q = __float2int_rn(fminf(fmaxf(v, -7.999f), 7.999f) * 4096.f);
            op[c * 256 + r] = (short)q;
        }
    }
}

// ---------------------------------------------------------------------------
// K0b: transpose unary_h [B,K,H,W] -> fp32 [B,K,W,H]
// ---------------------------------------------------------------------------
__global__ void k0_uh(const float* __restrict__ uh) {
    __shared__ float tile[32][33];
    int slab = blockIdx.z;
    int c0 = blockIdx.x * 32, r0 = blockIdx.y * 32;
    int tx = threadIdx.x, ty = threadIdx.y;
    const float* ip = uh + (long)slab * 65536;
    float* op = g_UhT + (long)slab * 65536;

    #pragma unroll
    for (int m = 0; m < 4; m++)
        tile[ty + 8*m][tx] = __ldcs(&ip[(r0 + ty + 8*m) * 256 + c0 + tx]);
    __syncthreads();
    #pragma unroll
    for (int m = 0; m < 4; m++)
        __stcs(&op[(c0 + ty + 8*m) * 256 + r0 + tx], tile[tx][ty + 8*m]);
}

// ---------------------------------------------------------------------------
// Chain scan worker. Block = 21 warps (state per warp) x 32 lanes (chains).
// Depth-3 cp.async smem pipeline; single barrier/step.
// QUANT=1: pairwise is s16 (value*4096), dequant folded into the FFMA scale.
// ---------------------------------------------------------------------------
template<int BWD, int QUANT>
__device__ __forceinline__ void scan_dir(const void* __restrict__ Pany,
    const float* __restrict__ U, float* __restrict__ AB,
    int b, int c0, int wid, int lane, float sc, float gl,
    void* Pb_, float* Ub, float* Sb)
{
    const long RS = BWD ? (long)SLAB_P : (long)KK * SLAB_P;   // row stride (elements)
    const int rowsel = BWD ? wid * KK : wid;
    const float* gPf = (const float*)Pany + ((long)(b * KK * KK) + rowsel) * SLAB_P + c0;
    const short* gPs = (const short*)Pany + ((long)(b * KK * KK) + rowsel) * SLAB_P + c0;
    const float* gU = U + ((long)(b * KK) + wid) * SLAB_U + c0;

    auto issue = [&](int s, int buf) {
        int e  = BWD ? (254 - s) : s;        // edge index
        int up = BWD ? (254 - s) : (s + 1);  // unary position
        if (QUANT) {
            const short* srcRow = gPs + (long)e * CDIM;
            int subrow = lane >> 2, chunk = lane & 3;    // 4 x 16B = 64B per row
            #pragma unroll
            for (int q = 0; q < 3; q++) {
                int row = q * 8 + subrow;
                cp16_pred((char*)Pb_ + (((buf * 21 + wid) * 21 + row) * 32 + chunk * 8) * 2,
                          srcRow + (long)row * RS + chunk * 8,
                          (unsigned)(row < KK));
            }
        } else {
            const float* srcRow = gPf + (long)e * CDIM;
            int subrow = lane >> 3, chunk = lane & 7;    // 8 x 16B = 128B per row
            #pragma unroll
            for (int q = 0; q < 6; q++) {
                int row = q * 4 + subrow;
                cp16_pred((char*)Pb_ + (((buf * 21 + wid) * 21 + row) * 32 + chunk * 4) * 4,
                          srcRow + (long)row * RS + chunk * 4,
                          (unsigned)(row < KK));
            }
        }
        cp16_pred(Ub + ((buf * 21 + wid) * 32 + (lane & 7) * 4),
                  gU + (long)up * CDIM + (lane & 7) * 4,
                  (unsigned)((lane >> 3) == 0));
        asm volatile("cp.async.commit_group;" ::: "memory");
    };

    issue(0, 0);
    issue(1, 1);

    // init state
    {
        int ipos = BWD ? (LDIM - 1) : 0;
        float u0 = gU[(long)ipos * CDIM + lane];
        Sb[wid * 32 + lane] = u0;                  // fwd: alpha0=u0 ; bwd: t=0+uL
        AB[((long)(b * KK) + wid) * SLAB_U + (long)ipos * CDIM + c0 + lane] = BWD ? 0.f : u0;
    }

    const float scp = QUANT ? sc * (1.0f / 4096.0f) : sc;
    int sb = 0;
    long abbase = ((long)(b * KK) + wid) * SLAB_U + c0 + lane;
    for (int s = 0; s < 255; s++) {
        int cur = s % 3;
        asm volatile("cp.async.wait_group 1;" ::: "memory");
        __syncthreads();   // step-s tile visible; prev state visible; buf (s+2)%3 free
        int nxt = s + 2; if (nxt > 254) nxt = 254;   // dup issue keeps group count uniform
        issue(nxt, (s + 2) % 3);

        float pj[KK], st[KK];
        if (QUANT) {
            const short* PbS = (const short*)Pb_;
            #pragma unroll
            for (int j = 0; j < KK; j++) pj[j] = (float)PbS[((cur * 21 + wid) * 21 + j) * 32 + lane];
        } else {
            const float* PbF = (const float*)Pb_;
            #pragma unroll
            for (int j = 0; j < KK; j++) pj[j] = PbF[((cur * 21 + wid) * 21 + j) * 32 + lane];
        }
        #pragma unroll
        for (int j = 0; j < KK; j++) st[j] = Sb[(sb * 21 + j) * 32 + lane];
        float un = Ub[(cur * 21 + wid) * 32 + lane];

        float mx = st[0];
        #pragma unroll
        for (int j = 1; j < KK; j++) mx = fmaxf(mx, st[j]);
        float nm = -mx * sc;
        float e0 = 0.f, e1 = 0.f, e2 = 0.f;
        #pragma unroll
        for (int j = 0; j < KK; j++) {
            float t = ex2f(fmaf(pj[j], scp, fmaf(st[j], sc, nm)));
            if (j % 3 == 0) e0 += t; else if (j % 3 == 1) e1 += t; else e2 += t;
        }
        float lse = fmaf(gl, lg2f((e0 + e1) + e2), mx);   // g*logsumexp((st+p)/g)

        int ipos = BWD ? (254 - s) : (s + 1);
        float outv, newstate;
        if (!BWD) { outv = lse + un; newstate = outv; }     // alpha_i
        else      { outv = lse;      newstate = lse + un; } // beta_i ; t = beta+u
        AB[abbase + (long)ipos * CDIM] = outv;
        Sb[((sb ^ 1) * 21 + wid) * 32 + lane] = newstate;
        sb ^= 1;
    }
    asm volatile("cp.async.wait_group 0;" ::: "memory");
}

// ---------------------------------------------------------------------------
// Scan kernel: 128 blocks = {fwd-h, bwd-h, fwd-v, bwd-v} x 32 chain-groups,
// all concurrent. h variants read quantized s16 pairwise.
// ---------------------------------------------------------------------------
__global__ __launch_bounds__(672, 1)
void scan_kernel(const float* __restrict__ Pv, const float* __restrict__ Uv,
                 const float* __restrict__ gamma) {
    extern __shared__ float sm[];
    float* Pb = sm;                        // fp32: [3][21][21][32] (s16 uses half)
    float* Ub = Pb + 3 * 21 * 21 * 32;     // [3][21][32]
    float* Sb = Ub + 3 * 21 * 32;          // [2][21][32]

    int wid  = threadIdx.x >> 5;
    int lane = threadIdx.x & 31;
    int variant = blockIdx.x >> 5;    // 0 fwd-h, 1 bwd-h, 2 fwd-v, 3 bwd-v
    int grp = blockIdx.x & 31;
    int b = grp >> 3;
    int c0 = (grp & 7) << 5;
    int isv = (variant >= 2) ? 1 : 0;
    int bwd = variant & 1;

    float g = fmaxf(gamma[0], 0.01f);
    float sc = (1.0f / g) * 1.4426950408889634f;  // 1/(g ln2)
    float gl = g * 0.6931471805599453f;           // g ln2

    if (isv) {
        if (bwd) scan_dir<1,0>(Pv, Uv, g_beta[1],  b, c0, wid, lane, sc, gl, Pb, Ub, Sb);
        else     scan_dir<0,0>(Pv, Uv, g_alpha[1], b, c0, wid, lane, sc, gl, Pb, Ub, Sb);
    } else {
        if (bwd) scan_dir<1,1>(g_PhT16, g_UhT, g_beta[0],  b, c0, wid, lane, sc, gl, Pb, Ub, Sb);
        else     scan_dir<0,1>(g_PhT16, g_UhT, g_alpha[0], b, c0, wid, lane, sc, gl, Pb, Ub, Sb);
    }
}

// ---------------------------------------------------------------------------
// Marginal for h direction: storage [b,k,w,h] -> output [b,k,h,w] via
// 32x32 smem tile so reads AND writes are coalesced. Writes mh only.
// ---------------------------------------------------------------------------
__global__ __launch_bounds__(1024)
void marg_h_kernel(float* __restrict__ out,
                   const float* __restrict__ gamma) {
    __shared__ float tile[32][33];
    int b = blockIdx.z;
    int w0 = blockIdx.y * 32, h0 = blockIdx.x * 32;
    int tx = threadIdx.x, ty = threadIdx.y;
    const float* A = g_alpha[0];
    const float* Bt = g_beta[0];
    float g = fmaxf(gamma[0], 0.01f);
    float sc = (1.0f / g) * 1.4426950408889634f;

    int base = b * KK * SLAB_U + (w0 + ty) * 256 + (h0 + tx);
    float s[KK];
    float m = -3.0e38f;
    #pragma unroll
    for (int k = 0; k < KK; k++) {
        s[k] = __ldcs(&A[base + k * SLAB_U]) + __ldcs(&Bt[base + k * SLAB_U]);
        m = fmaxf(m, s[k]);
    }
    float nm = -m * sc;
    float sum = 0.f;
    #pragma unroll
    for (int k = 0; k < KK; k++) {
        s[k] = ex2f(fmaf(s[k], sc, nm));
        sum += s[k];
    }
    float inv = __fdividef(1.0f, sum);

    int wbase = b * KK * SLAB_U + (h0 + ty) * 256 + (w0 + tx);
    #pragma unroll
    for (int k = 0; k < KK; k++) {
        __syncthreads();
        tile[ty][tx] = s[k] * inv;
        __syncthreads();
        out[wbase + k * SLAB_U] = tile[tx][ty];
    }
}

// ---------------------------------------------------------------------------
// Marginal for v direction fused with combine. Runs AFTER marg_h.
// Computes mv, then new_uh = uh - (mh-mv)/512, new_uv = uv + (mh-mv)/512.
// ---------------------------------------------------------------------------
__global__ void marg_v_combine_kernel(const float* __restrict__ uh,
                                      const float* __restrict__ uv,
                                      float* __restrict__ out,
                                      const float* __restrict__ gamma) {
    int idx = blockIdx.x * blockDim.x + threadIdx.x;
    if (idx >= BDIM * SLAB_U) return;
    int b = idx >> 16;
    int r = idx & 65535;
    const float* A = g_alpha[1];
    const float* Bt = g_beta[1];
    float g = fmaxf(gamma[0], 0.01f);
    float sc = (1.0f / g) * 1.4426950408889634f;

    int base = b * KK * SLAB_U + r;
    float s[KK];
    float m = -3.0e38f;
    #pragma unroll
    for (int k = 0; k < KK; k++) {
        s[k] = __ldcs(&A[base + k * SLAB_U]) + __ldcs(&Bt[base + k * SLAB_U]);
        m = fmaxf(m, s[k]);
    }
    float nm = -m * sc;
    float sum = 0.f;
    #pragma unroll
    for (int k = 0; k < KK; k++) {
        s[k] = ex2f(fmaf(s[k], sc, nm));
        sum += s[k];
    }
    float inv = __fdividef(1.0f, sum);

    const float* mh   = out + 2 * (size_t)S_ELEMS;
    float* mv_out     = out + 3 * (size_t)S_ELEMS;
    const float cc = 1.0f / 512.0f;
    #pragma unroll
    for (int k = 0; k < KK; k++) {
        int o = base + k * SLAB_U;
        float mvv = s[k] * inv;
        mv_out[o] = mvv;
        float d = (mh[o] - mvv) * cc;
        out[o] = uh[o] - d;                          // new_uh
        out[o + (size_t)S_ELEMS] = uv[o] + d;        // new_uv
    }
}

extern "C" void kernel_launch(void* const* d_in, const int* in_sizes, int n_in,
                              void* d_out, int out_size) {
    const float* uh    = (const float*)d_in[0];
    const float* uv    = (const float*)d_in[1];
    const float* ph    = (const float*)d_in[2];
    const float* pv    = (const float*)d_in[3];
    const float* gamma = (const float*)d_in[4];
    float* out = (float*)d_out;

    // 1) Transpose+quantize pairwise_h -> s16 [B,K,K,w,h]
    {
        dim3 grid(8, 8, BDIM * KK * KK);
        dim3 blk(32, 8);
        k0_ph<<<grid, blk>>>(ph);
    }
    // 2) Transpose unary_h -> [B,K,w,h]
    {
        dim3 grid(8, 8, BDIM * KK);
        dim3 blk(32, 8);
        k0_uh<<<grid, blk>>>(uh);
    }
    // 3) All four scans concurrently with deep cp.async pipeline
    {
        const int smem_bytes = (3*21*21*32 + 3*21*32 + 2*21*32) * 4;  // 182,784
        cudaFuncSetAttribute(scan_kernel, cudaFuncAttributeMaxDynamicSharedMemorySize, smem_bytes);
        scan_kernel<<<128, 672, smem_bytes>>>(pv, uv, gamma);
    }
    // 4) mh (offset 2S) via tiled-transpose marginal
    {
        dim3 grid(8, 8, BDIM);
        dim3 blk(32, 32);
        marg_h_kernel<<<grid, blk>>>(out + 2 * (size_t)S_ELEMS, gamma);
    }
    // 5) mv (offset 3S) + combine -> new_uh (0), new_uv (S)
    {
        int n = BDIM * SLAB_U;
        int blocks = (n + 255) / 256;
        marg_v_combine_kernel<<<blocks, 256>>>(uh, uv, out, gamma);
    }
    (void)in_sizes; (void)n_in; (void)out_size;
}

// round 16
// speedup vs baseline: 1.3126x; 1.0467x over previous
#include <cuda_runtime.h>

#define KK 21
#define LDIM 256
#define CDIM 256
#define BDIM 4
#define EDGES 255
#define SLAB_P (EDGES*CDIM)          // 65280
#define SLAB_U (LDIM*CDIM)           // 65536
#define S_ELEMS (BDIM*KK*LDIM*CDIM)  // 5,505,024
#define P_ELEMS (BDIM*KK*KK*EDGES*CDIM) // 115,153,920

// Scratch (device globals: no allocation allowed)
__device__ short g_PhT16[P_ELEMS];     // pairwise_h transposed+quantized: [B,K,K,w,h], value*4096
__device__ float g_UhT[S_ELEMS];       // unary_h transposed: [B,K,w,h]
__device__ float g_alpha[2][S_ELEMS];  // [dir][b,k,step,chain]  dir0=h, dir1=v
__device__ float g_beta[2][S_ELEMS];

__device__ __forceinline__ float ex2f(float x){ float y; asm("ex2.approx.f32 %0, %1;" : "=f"(y) : "f"(x)); return y; }
__device__ __forceinline__ float lg2f(float x){ float y; asm("lg2.approx.f32 %0, %1;" : "=f"(y) : "f"(x)); return y; }

__device__ __forceinline__ void cp16_pred(void* dst, const void* src, unsigned pred){
    unsigned su = (unsigned)__cvta_generic_to_shared(dst);
    asm volatile("{.reg .pred p; setp.ne.u32 p, %2, 0; @p cp.async.cg.shared.global [%0], [%1], 16;}"
                 :: "r"(su), "l"(src), "r"(pred));
}

// ---------------------------------------------------------------------------
// K0a: transpose + quantize pairwise_h [B,K,K,H,255] -> s16 [B,K,K,255,H]
// ---------------------------------------------------------------------------
__global__ void k0_ph(const float* __restrict__ ph) {
    __shared__ float tile[32][33];
    int slab = blockIdx.z;
    int c0 = blockIdx.x * 32, r0 = blockIdx.y * 32;
    int tx = threadIdx.x, ty = threadIdx.y;
    const float* ip = ph + (long)slab * (256 * 255);
    short* op = g_PhT16 + (long)slab * (255 * 256);

    #pragma unroll
    for (int m = 0; m < 4; m++) {
        int r = r0 + ty + 8*m, c = c0 + tx;
        if (c < 255) tile[ty + 8*m][tx] = __ldcs(&ip[r * 255 + c]);
    }
    __syncthreads();
    #pragma unroll
    for (int m = 0; m < 4; m++) {
        int c = c0 + ty + 8*m, r = r0 + tx;
        if (c < 255) {
            float v = tile[tx][ty + 8*m];
            int q = __float2int_rn(fminf(fmaxf(v, -7.999f), 7.999f) * 4096.f);
            op[c * 256 + r] = (short)q;
        }
    }
}

// ---------------------------------------------------------------------------
// K0b: transpose unary_h [B,K,H,W] -> fp32 [B,K,W,H]
// ---------------------------------------------------------------------------
__global__ void k0_uh(const float* __restrict__ uh) {
    __shared__ float tile[32][33];
    int slab = blockIdx.z;
    int c0 = blockIdx.x * 32, r0 = blockIdx.y * 32;
    int tx = threadIdx.x, ty = threadIdx.y;
    const float* ip = uh + (long)slab * 65536;
    float* op = g_UhT + (long)slab * 65536;

    #pragma unroll
    for (int m = 0; m < 4; m++)
        tile[ty + 8*m][tx] = __ldcs(&ip[(r0 + ty + 8*m) * 256 + c0 + tx]);
    __syncthreads();
    #pragma unroll
    for (int m = 0; m < 4; m++)
        __stcs(&op[(c0 + ty + 8*m) * 256 + r0 + tx], tile[tx][ty + 8*m]);
}

// ---------------------------------------------------------------------------
// Chain scan worker. Block = 21 warps (state per warp) x 32 lanes (chains).
// cp.async smem pipeline (STAGES deep, DIST prefetch distance); one barrier/step.
// QUANT=1: pairwise is s16 (value*4096). Dequant via magic-number LOP3+FSUB
// (exact, no conversion-pipe I2F).
// ---------------------------------------------------------------------------
template<int BWD, int QUANT, int DIST, int STAGES>
__device__ __forceinline__ void scan_dir(const void* __restrict__ Pany,
    const float* __restrict__ U, float* __restrict__ AB,
    int b, int c0, int wid, int lane, float sc, float gl,
    void* Pb_, float* Ub, float* Sb)
{
    const long RS = BWD ? (long)SLAB_P : (long)KK * SLAB_P;   // row stride (elements)
    const int rowsel = BWD ? wid * KK : wid;
    const float* gPf = (const float*)Pany + ((long)(b * KK * KK) + rowsel) * SLAB_P + c0;
    const short* gPs = (const short*)Pany + ((long)(b * KK * KK) + rowsel) * SLAB_P + c0;
    const float* gU = U + ((long)(b * KK) + wid) * SLAB_U + c0;

    auto issue = [&](int s, int buf) {
        int e  = BWD ? (254 - s) : s;        // edge index
        int up = BWD ? (254 - s) : (s + 1);  // unary position
        if (QUANT) {
            const short* srcRow = gPs + (long)e * CDIM;
            int subrow = lane >> 2, chunk = lane & 3;    // 4 x 16B = 64B per row
            #pragma unroll
            for (int q = 0; q < 3; q++) {
                int row = q * 8 + subrow;
                cp16_pred((char*)Pb_ + (((buf * 21 + wid) * 21 + row) * 32 + chunk * 8) * 2,
                          srcRow + (long)row * RS + chunk * 8,
                          (unsigned)(row < KK));
            }
        } else {
            const float* srcRow = gPf + (long)e * CDIM;
            int subrow = lane >> 3, chunk = lane & 7;    // 8 x 16B = 128B per row
            #pragma unroll
            for (int q = 0; q < 6; q++) {
                int row = q * 4 + subrow;
                cp16_pred((char*)Pb_ + (((buf * 21 + wid) * 21 + row) * 32 + chunk * 4) * 4,
                          srcRow + (long)row * RS + chunk * 4,
                          (unsigned)(row < KK));
            }
        }
        cp16_pred(Ub + ((buf * 21 + wid) * 32 + (lane & 7) * 4),
                  gU + (long)up * CDIM + (lane & 7) * 4,
                  (unsigned)((lane >> 3) == 0));
        asm volatile("cp.async.commit_group;" ::: "memory");
    };

    #pragma unroll
    for (int d = 0; d < DIST; d++) issue(d, d);

    // init state
    {
        int ipos = BWD ? (LDIM - 1) : 0;
        float u0 = gU[(long)ipos * CDIM + lane];
        Sb[wid * 32 + lane] = u0;                  // fwd: alpha0=u0 ; bwd: t=0+uL
        AB[((long)(b * KK) + wid) * SLAB_U + (long)ipos * CDIM + c0 + lane] = BWD ? 0.f : u0;
    }

    const float scp = QUANT ? sc * (1.0f / 4096.0f) : sc;
    int sb = 0;
    int cur = 0, nbuf = DIST % STAGES;
    long abbase = ((long)(b * KK) + wid) * SLAB_U + c0 + lane;
    for (int s = 0; s < 255; s++) {
        asm volatile("cp.async.wait_group %0;" :: "n"(DIST - 1));
        __syncthreads();   // step-s tile visible; prev state visible; buf nbuf free
        int nxt = s + DIST; if (nxt > 254) nxt = 254;   // dup issue keeps group count uniform
        issue(nxt, nbuf);
        if (++nbuf == STAGES) nbuf = 0;

        float pj[KK], st[KK];
        if (QUANT) {
            const short* PbS = (const short*)Pb_;
            #pragma unroll
            for (int j = 0; j < KK; j++) {
                unsigned z = (unsigned)(unsigned short)PbS[((cur * 21 + wid) * 21 + j) * 32 + lane];
                // exact dequant: bits = 2^23*1.5 | (q+32768)  ->  float - 12615680 == (float)q
                pj[j] = __uint_as_float((z ^ 0x8000u) | 0x4B400000u) - 12615680.0f;
            }
        } else {
            const float* PbF = (const float*)Pb_;
            #pragma unroll
            for (int j = 0; j < KK; j++) pj[j] = PbF[((cur * 21 + wid) * 21 + j) * 32 + lane];
        }
        #pragma unroll
        for (int j = 0; j < KK; j++) st[j] = Sb[(sb * 21 + j) * 32 + lane];
        float un = Ub[(cur * 21 + wid) * 32 + lane];
        if (++cur == STAGES) cur = 0;

        float mx = st[0];
        #pragma unroll
        for (int j = 1; j < KK; j++) mx = fmaxf(mx, st[j]);
        float nm = -mx * sc;
        float e0 = 0.f, e1 = 0.f, e2 = 0.f;
        #pragma unroll
        for (int j = 0; j < KK; j++) {
            float t = ex2f(fmaf(pj[j], scp, fmaf(st[j], sc, nm)));
            if (j % 3 == 0) e0 += t; else if (j % 3 == 1) e1 += t; else e2 += t;
        }
        float lse = fmaf(gl, lg2f((e0 + e1) + e2), mx);   // g*logsumexp((st+p)/g)

        int ipos = BWD ? (254 - s) : (s + 1);
        float outv, newstate;
        if (!BWD) { outv = lse + un; newstate = outv; }     // alpha_i
        else      { outv = lse;      newstate = lse + un; } // beta_i ; t = beta+u
        AB[abbase + (long)ipos * CDIM] = outv;
        Sb[((sb ^ 1) * 21 + wid) * 32 + lane] = newstate;
        sb ^= 1;
    }
    asm volatile("cp.async.wait_group 0;" ::: "memory");
}

// ---------------------------------------------------------------------------
// Scan kernel: 128 blocks = {fwd-h, bwd-h, fwd-v, bwd-v} x 32 chain-groups,
// all concurrent. h variants: s16 pairwise, 6-stage pipeline (dist 5);
// v variants: fp32 pairwise, 3-stage pipeline (dist 2).
// ---------------------------------------------------------------------------
__global__ __launch_bounds__(672, 1)
void scan_kernel(const float* __restrict__ Pv, const float* __restrict__ Uv,
                 const float* __restrict__ gamma) {
    extern __shared__ float sm[];
    // union layout: Pb max(6*28224B s16, 3*56448B fp32) = 169,344 B
    //               Ub max(6, 3 stages) * 2688 B = 16,128 B ; Sb 5,376 B
    float* Pb = sm;
    float* Ub = Pb + 169344 / 4;
    float* Sb = Ub + 16128 / 4;

    int wid  = threadIdx.x >> 5;
    int lane = threadIdx.x & 31;
    int variant = blockIdx.x >> 5;    // 0 fwd-h, 1 bwd-h, 2 fwd-v, 3 bwd-v
    int grp = blockIdx.x & 31;
    int b = grp >> 3;
    int c0 = (grp & 7) << 5;
    int isv = (variant >= 2) ? 1 : 0;
    int bwd = variant & 1;

    float g = fmaxf(gamma[0], 0.01f);
    float sc = (1.0f / g) * 1.4426950408889634f;  // 1/(g ln2)
    float gl = g * 0.6931471805599453f;           // g ln2

    if (isv) {
        if (bwd) scan_dir<1,0,2,3>(Pv, Uv, g_beta[1],  b, c0, wid, lane, sc, gl, Pb, Ub, Sb);
        else     scan_dir<0,0,2,3>(Pv, Uv, g_alpha[1], b, c0, wid, lane, sc, gl, Pb, Ub, Sb);
    } else {
        if (bwd) scan_dir<1,1,5,6>(g_PhT16, g_UhT, g_beta[0],  b, c0, wid, lane, sc, gl, Pb, Ub, Sb);
        else     scan_dir<0,1,5,6>(g_PhT16, g_UhT, g_alpha[0], b, c0, wid, lane, sc, gl, Pb, Ub, Sb);
    }
}

// ---------------------------------------------------------------------------
// Marginal for h direction: storage [b,k,w,h] -> output [b,k,h,w] via
// 32x32 smem tile so reads AND writes are coalesced. Writes mh only.
// ---------------------------------------------------------------------------
__global__ __launch_bounds__(1024)
void marg_h_kernel(float* __restrict__ out,
                   const float* __restrict__ gamma) {
    __shared__ float tile[32][33];
    int b = blockIdx.z;
    int w0 = blockIdx.y * 32, h0 = blockIdx.x * 32;
    int tx = threadIdx.x, ty = threadIdx.y;
    const float* A = g_alpha[0];
    const float* Bt = g_beta[0];
    float g = fmaxf(gamma[0], 0.01f);
    float sc = (1.0f / g) * 1.4426950408889634f;

    int base = b * KK * SLAB_U + (w0 + ty) * 256 + (h0 + tx);
    float s[KK];
    float m = -3.0e38f;
    #pragma unroll
    for (int k = 0; k < KK; k++) {
        s[k] = __ldcs(&A[base + k * SLAB_U]) + __ldcs(&Bt[base + k * SLAB_U]);
        m = fmaxf(m, s[k]);
    }
    float nm = -m * sc;
    float sum = 0.f;
    #pragma unroll
    for (int k = 0; k < KK; k++) {
        s[k] = ex2f(fmaf(s[k], sc, nm));
        sum += s[k];
    }
    float inv = __fdividef(1.0f, sum);

    int wbase = b * KK * SLAB_U + (h0 + ty) * 256 + (w0 + tx);
    #pragma unroll
    for (int k = 0; k < KK; k++) {
        __syncthreads();
        tile[ty][tx] = s[k] * inv;
        __syncthreads();
        out[wbase + k * SLAB_U] = tile[tx][ty];
    }
}

// ---------------------------------------------------------------------------
// Marginal for v direction fused with combine. Runs AFTER marg_h.
// Computes mv, then new_uh = uh - (mh-mv)/512, new_uv = uv + (mh-mv)/512.
// ---------------------------------------------------------------------------
__global__ void marg_v_combine_kernel(const float* __restrict__ uh,
                                      const float* __restrict__ uv,
                                      float* __restrict__ out,
                                      const float* __restrict__ gamma) {
    int idx = blockIdx.x * blockDim.x + threadIdx.x;
    if (idx >= BDIM * SLAB_U) return;
    int b = idx >> 16;
    int r = idx & 65535;
    const float* A = g_alpha[1];
    const float* Bt = g_beta[1];
    float g = fmaxf(gamma[0], 0.01f);
    float sc = (1.0f / g) * 1.4426950408889634f;

    int base = b * KK * SLAB_U + r;
    float s[KK];
    float m = -3.0e38f;
    #pragma unroll
    for (int k = 0; k < KK; k++) {
        s[k] = __ldcs(&A[base + k * SLAB_U]) + __ldcs(&Bt[base + k * SLAB_U]);
        m = fmaxf(m, s[k]);
    }
    float nm = -m * sc;
    float sum = 0.f;
    #pragma unroll
    for (int k = 0; k < KK; k++) {
        s[k] = ex2f(fmaf(s[k], sc, nm));
        sum += s[k];
    }
    float inv = __fdividef(1.0f, sum);

    const float* mh   = out + 2 * (size_t)S_ELEMS;
    float* mv_out     = out + 3 * (size_t)S_ELEMS;
    const float cc = 1.0f / 512.0f;
    #pragma unroll
    for (int k = 0; k < KK; k++) {
        int o = base + k * SLAB_U;
        float mvv = s[k] * inv;
        mv_out[o] = mvv;
        float d = (mh[o] - mvv) * cc;
        out[o] = uh[o] - d;                          // new_uh
        out[o + (size_t)S_ELEMS] = uv[o] + d;        // new_uv
    }
}

extern "C" void kernel_launch(void* const* d_in, const int* in_sizes, int n_in,
                              void* d_out, int out_size) {
    const float* uh    = (const float*)d_in[0];
    const float* uv    = (const float*)d_in[1];
    const float* ph    = (const float*)d_in[2];
    const float* pv    = (const float*)d_in[3];
    const float* gamma = (const float*)d_in[4];
    float* out = (float*)d_out;

    // 1) Transpose+quantize pairwise_h -> s16 [B,K,K,w,h]
    {
        dim3 grid(8, 8, BDIM * KK * KK);
        dim3 blk(32, 8);
        k0_ph<<<grid, blk>>>(ph);
    }
    // 2) Transpose unary_h -> [B,K,w,h]
    {
        dim3 grid(8, 8, BDIM * KK);
        dim3 blk(32, 8);
        k0_uh<<<grid, blk>>>(uh);
    }
    // 3) All four scans concurrently with deep cp.async pipeline
    {
        const int smem_bytes = 169344 + 16128 + 5376;  // 190,848
        cudaFuncSetAttribute(scan_kernel, cudaFuncAttributeMaxDynamicSharedMemorySize, smem_bytes);
        scan_kernel<<<128, 672, smem_bytes>>>(pv, uv, gamma);
    }
    // 4) mh (offset 2S) via tiled-transpose marginal
    {
        dim3 grid(8, 8, BDIM);
        dim3 blk(32, 32);
        marg_h_kernel<<<grid, blk>>>(out + 2 * (size_t)S_ELEMS, gamma);
    }
    // 5) mv (offset 3S) + combine -> new_uh (0), new_uv (S)
    {
        int n = BDIM * SLAB_U;
        int blocks = (n + 255) / 256;
        marg_v_combine_kernel<<<blocks, 256>>>(uh, uv, out, gamma);
    }
    (void)in_sizes; (void)n_in; (void)out_size;
}

// round 17
// speedup vs baseline: 1.3779x; 1.0498x over previous
#include <cuda_runtime.h>

#define KK 21
#define LDIM 256
#define CDIM 256
#define BDIM 4
#define EDGES 255
#define SLAB_P (EDGES*CDIM)          // 65280
#define SLAB_U (LDIM*CDIM)           // 65536
#define S_ELEMS (BDIM*KK*LDIM*CDIM)  // 5,505,024
#define P_ELEMS (BDIM*KK*KK*EDGES*CDIM) // 115,153,920

// Scratch (device globals: no allocation allowed)
__device__ unsigned short g_PhE[P_ELEMS];  // exp(pairwise_h/g) transposed: [B,K,K,w,h] bf16
__device__ float g_EUhT[S_ELEMS];          // exp(unary_h/g) transposed: [B,K,w,h]
__device__ float g_EUv[S_ELEMS];           // exp(unary_v/g): [B,K,h,w]
__device__ float g_F[2][S_ELEMS];          // forward prob messages [dir][b,k,pos,chain]
__device__ float g_B[2][S_ELEMS];          // backward prob messages

__device__ __forceinline__ float ex2f(float x){ float y; asm("ex2.approx.f32 %0, %1;" : "=f"(y) : "f"(x)); return y; }

__device__ __forceinline__ unsigned short f2bf(float f){
    unsigned u = __float_as_uint(f);
    unsigned r = u + 0x7FFFu + ((u >> 16) & 1u);
    return (unsigned short)(r >> 16);
}

__device__ __forceinline__ void cp16_pred(void* dst, const void* src, unsigned pred){
    unsigned su = (unsigned)__cvta_generic_to_shared(dst);
    asm volatile("{.reg .pred p; setp.ne.u32 p, %2, 0; @p cp.async.cg.shared.global [%0], [%1], 16;}"
                 :: "r"(su), "l"(src), "r"(pred));
}

// ---------------------------------------------------------------------------
// K0a: transpose pairwise_h [B,K,K,H,255] -> bf16 exp(p/g) [B,K,K,255,H]
// ---------------------------------------------------------------------------
__global__ void k0_ph(const float* __restrict__ ph, const float* __restrict__ gamma) {
    __shared__ float tile[32][33];
    float g = fmaxf(gamma[0], 0.01f);
    float sc = (1.0f / g) * 1.4426950408889634f;
    int slab = blockIdx.z;
    int c0 = blockIdx.x * 32, r0 = blockIdx.y * 32;
    int tx = threadIdx.x, ty = threadIdx.y;
    const float* ip = ph + (long)slab * (256 * 255);
    unsigned short* op = g_PhE + (long)slab * (255 * 256);

    #pragma unroll
    for (int m = 0; m < 4; m++) {
        int r = r0 + ty + 8*m, c = c0 + tx;
        if (c < 255) tile[ty + 8*m][tx] = __ldcs(&ip[r * 255 + c]);
    }
    __syncthreads();
    #pragma unroll
    for (int m = 0; m < 4; m++) {
        int c = c0 + ty + 8*m, r = r0 + tx;
        if (c < 255) {
            float a = tile[tx][ty + 8*m] * sc;
            a = fminf(fmaxf(a, -60.f), 60.f);
            op[c * 256 + r] = f2bf(ex2f(a));
        }
    }
}

// ---------------------------------------------------------------------------
// K0b: transpose unary_h [B,K,H,W] -> fp32 exp(u/g) [B,K,W,H]
// ---------------------------------------------------------------------------
__global__ void k0_uh(const float* __restrict__ uh, const float* __restrict__ gamma) {
    __shared__ float tile[32][33];
    float g = fmaxf(gamma[0], 0.01f);
    float sc = (1.0f / g) * 1.4426950408889634f;
    int slab = blockIdx.z;
    int c0 = blockIdx.x * 32, r0 = blockIdx.y * 32;
    int tx = threadIdx.x, ty = threadIdx.y;
    const float* ip = uh + (long)slab * 65536;
    float* op = g_EUhT + (long)slab * 65536;

    #pragma unroll
    for (int m = 0; m < 4; m++)
        tile[ty + 8*m][tx] = __ldcs(&ip[(r0 + ty + 8*m) * 256 + c0 + tx]);
    __syncthreads();
    #pragma unroll
    for (int m = 0; m < 4; m++) {
        float a = tile[tx][ty + 8*m] * sc;
        a = fminf(fmaxf(a, -60.f), 60.f);
        __stcs(&op[(c0 + ty + 8*m) * 256 + r0 + tx], ex2f(a));
    }
}

// ---------------------------------------------------------------------------
// K0c: elementwise exp(unary_v/g)
// ---------------------------------------------------------------------------
__global__ void k0_uv(const float* __restrict__ uv, const float* __restrict__ gamma) {
    float g = fmaxf(gamma[0], 0.01f);
    float sc = (1.0f / g) * 1.4426950408889634f;
    int idx = blockIdx.x * blockDim.x + threadIdx.x;
    if (idx >= S_ELEMS / 4) return;
    float4 v = ((const float4*)uv)[idx];
    float4 o;
    o.x = ex2f(fminf(fmaxf(v.x * sc, -60.f), 60.f));
    o.y = ex2f(fminf(fmaxf(v.y * sc, -60.f), 60.f));
    o.z = ex2f(fminf(fmaxf(v.z * sc, -60.f), 60.f));
    o.w = ex2f(fminf(fmaxf(v.w * sc, -60.f), 60.f));
    ((float4*)g_EUv)[idx] = o;
}

// ---------------------------------------------------------------------------
// Prob-domain chain scan. Block = 21 warps (one state per warp) x 32 lanes.
// fwd: F'_k = eu_k * (sum_j F_j E_jk) / (sum_j F_j)        (store F')
// bwd: B_j  = (sum_k E_jk * S_k) / (sum_k S_k), S = eu*B   (store B)
// EH=1: E is bf16 in gmem (h dir). EH=0: E computed as ex2(p*sc) (v dir).
// ---------------------------------------------------------------------------
template<int BWD, int EH, int DIST, int STAGES>
__device__ __forceinline__ void scan_dir(const void* __restrict__ Pany,
    const float* __restrict__ EU, float* __restrict__ AB,
    int b, int c0, int wid, int lane, float sc,
    void* Pb_, float* Ub, float* Sb)
{
    const long RS = BWD ? (long)SLAB_P : (long)KK * SLAB_P;   // stride between summation idx
    const int rowsel = BWD ? wid * KK : wid;
    const float* gPf = (const float*)Pany + ((long)(b * KK * KK) + rowsel) * SLAB_P + c0;
    const unsigned short* gPe = (const unsigned short*)Pany + ((long)(b * KK * KK) + rowsel) * SLAB_P + c0;
    const float* gU = EU + ((long)(b * KK) + wid) * SLAB_U + c0;

    auto issue = [&](int s, int buf) {
        int e  = BWD ? (254 - s) : s;        // edge index
        int up = BWD ? (254 - s) : (s + 1);  // unary position
        if (EH) {
            const unsigned short* srcRow = gPe + (long)e * CDIM;
            int subrow = lane >> 2, chunk = lane & 3;    // 4 x 16B = 64B per row
            #pragma unroll
            for (int q = 0; q < 3; q++) {
                int row = q * 8 + subrow;
                cp16_pred((char*)Pb_ + (((buf * 21 + wid) * 21 + row) * 32 + chunk * 8) * 2,
                          srcRow + (long)row * RS + chunk * 8,
                          (unsigned)(row < KK));
            }
        } else {
            const float* srcRow = gPf + (long)e * CDIM;
            int subrow = lane >> 3, chunk = lane & 7;    // 8 x 16B = 128B per row
            #pragma unroll
            for (int q = 0; q < 6; q++) {
                int row = q * 4 + subrow;
                cp16_pred((char*)Pb_ + (((buf * 21 + wid) * 21 + row) * 32 + chunk * 4) * 4,
                          srcRow + (long)row * RS + chunk * 4,
                          (unsigned)(row < KK));
            }
        }
        cp16_pred(Ub + ((buf * 21 + wid) * 32 + (lane & 7) * 4),
                  gU + (long)up * CDIM + (lane & 7) * 4,
                  (unsigned)((lane >> 3) == 0));
        asm volatile("cp.async.commit_group;" ::: "memory");
    };

    #pragma unroll
    for (int d = 0; d < DIST; d++) issue(d, d);

    // init state
    {
        int ipos = BWD ? (LDIM - 1) : 0;
        float eu0 = gU[(long)ipos * CDIM + lane];
        // fwd: state = F_0 = eu_0, output F_0 = eu_0
        // bwd: B_{L-1} = 1, state = eu_{L-1} * 1
        Sb[wid * 32 + lane] = eu0;
        AB[((long)(b * KK) + wid) * SLAB_U + (long)ipos * CDIM + c0 + lane] = BWD ? 1.0f : eu0;
    }

    int sb = 0;
    int cur = 0, nbuf = DIST % STAGES;
    long abbase = ((long)(b * KK) + wid) * SLAB_U + c0 + lane;
    for (int s = 0; s < 255; s++) {
        asm volatile("cp.async.wait_group %0;" :: "n"(DIST - 1));
        __syncthreads();
        int nxt = s + DIST; if (nxt > 254) nxt = 254;
        issue(nxt, nbuf);
        if (++nbuf == STAGES) nbuf = 0;

        const unsigned short* PbS = (const unsigned short*)Pb_ + ((cur * 21 + wid) * 21) * 32 + lane;
        const float* PbF = (const float*)Pb_ + ((cur * 21 + wid) * 21) * 32 + lane;

        float t0 = 0.f, t1 = 0.f, t2 = 0.f;      // sum of state
        float d0 = 0.f, d1 = 0.f, d2 = 0.f;      // dot(E, state)
        #pragma unroll
        for (int j = 0; j < KK; j++) {
            float tj = Sb[(sb * 21 + j) * 32 + lane];
            float E;
            if (EH) E = __uint_as_float((unsigned)PbS[j * 32] << 16);
            else    E = ex2f(PbF[j * 32] * sc);
            if (j % 3 == 0)      { t0 += tj; d0 = fmaf(E, tj, d0); }
            else if (j % 3 == 1) { t1 += tj; d1 = fmaf(E, tj, d1); }
            else                 { t2 += tj; d2 = fmaf(E, tj, d2); }
        }
        float sumt = (t0 + t1) + t2;
        float dot  = (d0 + d1) + d2;
        float r = __fdividef(1.0f, sumt);
        float eu = Ub[(cur * 21 + wid) * 32 + lane];
        if (++cur == STAGES) cur = 0;

        int ipos = BWD ? (254 - s) : (s + 1);
        float outv, ns;
        if (!BWD) { outv = eu * dot * r; ns = outv; }      // F_i
        else      { outv = dot * r;      ns = outv * eu; } // B_i ; state = eu_i*B_i
        AB[abbase + (long)ipos * CDIM] = outv;
        Sb[((sb ^ 1) * 21 + wid) * 32 + lane] = ns;
        sb ^= 1;
    }
    asm volatile("cp.async.wait_group 0;" ::: "memory");
}

// ---------------------------------------------------------------------------
// Scan kernel: 128 blocks = {fwd-h, bwd-h, fwd-v, bwd-v} x 32 chain-groups.
// h: bf16 exp-table, 6-stage pipeline; v: fp32 pairwise + on-the-fly exp, 3-stage.
// ---------------------------------------------------------------------------
__global__ __launch_bounds__(672, 1)
void scan_kernel(const float* __restrict__ Pv, const float* __restrict__ gamma) {
    extern __shared__ float sm[];
    float* Pb = sm;                     // 169,344 B (6 x bf16 tile or 3 x fp32 tile)
    float* Ub = Pb + 169344 / 4;        // 16,128 B
    float* Sb = Ub + 16128 / 4;         // 5,376 B

    int wid  = threadIdx.x >> 5;
    int lane = threadIdx.x & 31;
    int variant = blockIdx.x >> 5;    // 0 fwd-h, 1 bwd-h, 2 fwd-v, 3 bwd-v
    int grp = blockIdx.x & 31;
    int b = grp >> 3;
    int c0 = (grp & 7) << 5;
    int isv = (variant >= 2) ? 1 : 0;
    int bwd = variant & 1;

    float g = fmaxf(gamma[0], 0.01f);
    float sc = (1.0f / g) * 1.4426950408889634f;

    if (isv) {
        if (bwd) scan_dir<1,0,2,3>(Pv, g_EUv, g_B[1], b, c0, wid, lane, sc, Pb, Ub, Sb);
        else     scan_dir<0,0,2,3>(Pv, g_EUv, g_F[1], b, c0, wid, lane, sc, Pb, Ub, Sb);
    } else {
        if (bwd) scan_dir<1,1,5,6>(g_PhE, g_EUhT, g_B[0], b, c0, wid, lane, sc, Pb, Ub, Sb);
        else     scan_dir<0,1,5,6>(g_PhE, g_EUhT, g_F[0], b, c0, wid, lane, sc, Pb, Ub, Sb);
    }
}

// ---------------------------------------------------------------------------
// h-marginal: m = normalize_k(F*B). Storage [b,k,w,h] -> output [b,k,h,w]
// via 32x32 smem tile. No exp needed in prob domain.
// ---------------------------------------------------------------------------
__global__ __launch_bounds__(1024)
void marg_h_kernel(float* __restrict__ out) {
    __shared__ float tile[32][33];
    int b = blockIdx.z;
    int w0 = blockIdx.y * 32, h0 = blockIdx.x * 32;
    int tx = threadIdx.x, ty = threadIdx.y;
    const float* F = g_F[0];
    const float* Bt = g_B[0];

    int base = b * KK * SLAB_U + (w0 + ty) * 256 + (h0 + tx);
    float s[KK];
    float sum = 0.f;
    #pragma unroll
    for (int k = 0; k < KK; k++) {
        s[k] = __ldcs(&F[base + k * SLAB_U]) * __ldcs(&Bt[base + k * SLAB_U]);
        sum += s[k];
    }
    float inv = __fdividef(1.0f, sum);

    int wbase = b * KK * SLAB_U + (h0 + ty) * 256 + (w0 + tx);
    #pragma unroll
    for (int k = 0; k < KK; k++) {
        __syncthreads();
        tile[ty][tx] = s[k] * inv;
        __syncthreads();
        out[wbase + k * SLAB_U] = tile[tx][ty];
    }
}

// ---------------------------------------------------------------------------
// v-marginal fused with combine. Runs AFTER marg_h.
// mv = normalize(F*B); new_uh = uh-(mh-mv)/512; new_uv = uv+(mh-mv)/512.
// ---------------------------------------------------------------------------
__global__ void marg_v_combine_kernel(const float* __restrict__ uh,
                                      const float* __restrict__ uv,
                                      float* __restrict__ out) {
    int idx = blockIdx.x * blockDim.x + threadIdx.x;
    if (idx >= BDIM * SLAB_U) return;
    int b = idx >> 16;
    int r = idx & 65535;
    const float* F = g_F[1];
    const float* Bt = g_B[1];

    int base = b * KK * SLAB_U + r;
    float s[KK];
    float sum = 0.f;
    #pragma unroll
    for (int k = 0; k < KK; k++) {
        s[k] = __ldcs(&F[base + k * SLAB_U]) * __ldcs(&Bt[base + k * SLAB_U]);
        sum += s[k];
    }
    float inv = __fdividef(1.0f, sum);

    const float* mh   = out + 2 * (size_t)S_ELEMS;
    float* mv_out     = out + 3 * (size_t)S_ELEMS;
    const float cc = 1.0f / 512.0f;
    #pragma unroll
    for (int k = 0; k < KK; k++) {
        int o = base + k * SLAB_U;
        float mvv = s[k] * inv;
        mv_out[o] = mvv;
        float d = (mh[o] - mvv) * cc;
        out[o] = uh[o] - d;                          // new_uh
        out[o + (size_t)S_ELEMS] = uv[o] + d;        // new_uv
    }
}

extern "C" void kernel_launch(void* const* d_in, const int* in_sizes, int n_in,
                              void* d_out, int out_size) {
    const float* uh    = (const float*)d_in[0];
    const float* uv    = (const float*)d_in[1];
    const float* ph    = (const float*)d_in[2];
    const float* pv    = (const float*)d_in[3];
    const float* gamma = (const float*)d_in[4];
    float* out = (float*)d_out;

    // 1) Transpose + exp pairwise_h -> bf16 E table
    {
        dim3 grid(8, 8, BDIM * KK * KK);
        dim3 blk(32, 8);
        k0_ph<<<grid, blk>>>(ph, gamma);
    }
    // 2) Transpose + exp unary_h
    {
        dim3 grid(8, 8, BDIM * KK);
        dim3 blk(32, 8);
        k0_uh<<<grid, blk>>>(uh, gamma);
    }
    // 3) exp unary_v
    {
        int n = S_ELEMS / 4;
        k0_uv<<<(n + 255) / 256, 256>>>(uv, gamma);
    }
    // 4) All four prob-domain scans concurrently
    {
        const int smem_bytes = 169344 + 16128 + 5376;  // 190,848
        cudaFuncSetAttribute(scan_kernel, cudaFuncAttributeMaxDynamicSharedMemorySize, smem_bytes);
        scan_kernel<<<128, 672, smem_bytes>>>(pv, gamma);
    }
    // 5) mh (offset 2S)
    {
        dim3 grid(8, 8, BDIM);
        dim3 blk(32, 32);
        marg_h_kernel<<<grid, blk>>>(out + 2 * (size_t)S_ELEMS);
    }
    // 6) mv (offset 3S) + combine -> new_uh (0), new_uv (S)
    {
        int n = BDIM * SLAB_U;
        marg_v_combine_kernel<<<(n + 255) / 256, 256>>>(uh, uv, out);
    }
    (void)in_sizes; (void)n_in; (void)out_size;
}